// round 5
// baseline (speedup 1.0000x reference)
#include <cuda_runtime.h>
#include <cstddef>

#define S_LEN   256
#define BATCH   256
#define HID     512
#define OUTD    64
#define NSTEP   63
#define KCAT    1088   // 64 (x) + 512 (ctx) + 512 (h)
#define KPAD    1280   // 16 splits * 80
#define KSPLIT  8      // q gemm split
#define KSPLITR 16     // rnn gemm split (klen 80)

typedef unsigned long long ull;

// ---------------- scratch (device globals: allocation-free rule) ----------------
__device__ float g_P[(size_t)S_LEN * BATCH * HID];
__device__ float g_qpart[KSPLIT * BATCH * HID];
__device__ float g_rnnpart[KSPLITR * BATCH * HID];
__device__ float g_rin[BATCH * KPAD];                 // [x | ctx | h | 0-pad]
__device__ float g_WcatT[KPAD * HID];
__device__ float g_bsum[HID];
__device__ float g_h0buf[BATCH * HID];
__device__ float g_h1buf[BATCH * HID];
__device__ float g_x0buf[BATCH * OUTD];
__device__ float g_x1buf[BATCH * OUTD];

__device__ __forceinline__ float fast_tanh(float x) {
    float e = __expf(2.0f * x);
    return 1.0f - __fdividef(2.0f, e + 1.0f);
}

// ---- packed f32x2 helpers (Blackwell FFMA2 path) ----
__device__ __forceinline__ ull pk2(float lo, float hi) {
    ull r; asm("mov.b64 %0, {%1, %2};" : "=l"(r) : "f"(lo), "f"(hi)); return r;
}
__device__ __forceinline__ ull fma2(ull a, ull b, ull c) {
    ull d; asm("fma.rn.f32x2 %0, %1, %2, %3;" : "=l"(d) : "l"(a), "l"(b), "l"(c)); return d;
}
__device__ __forceinline__ ull mul2(ull a, ull b) {
    ull d; asm("mul.rn.f32x2 %0, %1, %2;" : "=l"(d) : "l"(a), "l"(b)); return d;
}

// ============== P precompute: 128x128 tile, 8x8 microtile, db + FFMA2 ==============
__global__ void __launch_bounds__(256) gemm128(const float* __restrict__ A,
                                               const float* __restrict__ B,
                                               const float* __restrict__ bias,
                                               float* __restrict__ C,
                                               int M, int N, int K) {
    __shared__ __align__(16) float As[2][8][132];
    __shared__ __align__(16) float Bs[2][8][128];
    int t  = threadIdx.x;
    int tx = t & 15, ty = t >> 4;
    int m0 = blockIdx.x * 128, n0 = blockIdx.y * 128;

    int ar = t >> 1, ak = (t & 1) * 4;
    int br = t >> 5, bn = (t & 31) * 4;

    const float* Aptr = A + (size_t)(m0 + ar) * K + ak;
    const float* Bptr = B + (size_t)br * N + n0 + bn;

    // acc pairs along n: j = {tx*4, tx*4+2, 64+tx*4, 64+tx*4+2}
    ull accp[8][4];
#pragma unroll
    for (int jp = 0; jp < 4; jp++) {
        int n = n0 + ((jp < 2) ? tx * 4 + jp * 2 : 64 + tx * 4 + (jp - 2) * 2);
        ull bv = bias ? pk2(bias[n], bias[n + 1]) : 0ull;
#pragma unroll
        for (int i = 0; i < 8; i++) accp[i][jp] = bv;
    }

    float4 a_reg = *(const float4*)(Aptr);
    float4 b_reg = *(const float4*)(Bptr);
    As[0][ak + 0][ar] = a_reg.x;
    As[0][ak + 1][ar] = a_reg.y;
    As[0][ak + 2][ar] = a_reg.z;
    As[0][ak + 3][ar] = a_reg.w;
    *(float4*)(&Bs[0][br][bn]) = b_reg;
    __syncthreads();

    int nc = K / 8, buf = 0;
    for (int c = 0; c < nc; c++) {
        if (c + 1 < nc) {
            a_reg = *(const float4*)(Aptr + (c + 1) * 8);
            b_reg = *(const float4*)(Bptr + (size_t)(c + 1) * 8 * N);
        }
#pragma unroll
        for (int kk = 0; kk < 8; kk++) {
            float4 a0 = *(const float4*)(&As[buf][kk][ty * 4]);
            float4 a1 = *(const float4*)(&As[buf][kk][64 + ty * 4]);
            ulonglong2 bq0 = *(const ulonglong2*)(&Bs[buf][kk][tx * 4]);
            ulonglong2 bq1 = *(const ulonglong2*)(&Bs[buf][kk][64 + tx * 4]);
            float av[8] = {a0.x, a0.y, a0.z, a0.w, a1.x, a1.y, a1.z, a1.w};
            ull bp[4] = {bq0.x, bq0.y, bq1.x, bq1.y};
#pragma unroll
            for (int i = 0; i < 8; i++) {
                ull ap = pk2(av[i], av[i]);
#pragma unroll
                for (int jp = 0; jp < 4; jp++) accp[i][jp] = fma2(ap, bp[jp], accp[i][jp]);
            }
        }
        if (c + 1 < nc) {
            int nb = buf ^ 1;
            As[nb][ak + 0][ar] = a_reg.x;
            As[nb][ak + 1][ar] = a_reg.y;
            As[nb][ak + 2][ar] = a_reg.z;
            As[nb][ak + 3][ar] = a_reg.w;
            *(float4*)(&Bs[nb][br][bn]) = b_reg;
        }
        __syncthreads();
        buf ^= 1;
    }

#pragma unroll
    for (int i = 0; i < 8; i++) {
        int m = m0 + ((i < 4) ? ty * 4 + i : 64 + ty * 4 + (i - 4));
        *(ulonglong2*)(C + (size_t)m * N + n0 + tx * 4)      = make_ulonglong2(accp[i][0], accp[i][1]);
        *(ulonglong2*)(C + (size_t)m * N + n0 + 64 + tx * 4) = make_ulonglong2(accp[i][2], accp[i][3]);
    }
}

// ============== single-stage full-K-slice skinny GEMM (split-K) ==============
// 64x64 tile, 4x4 microtile (n packed as 2 f32x2), grid (M/64, N/64, nsplit).
template <int KLEN>
__global__ void __launch_bounds__(256) gemmsk(const float* __restrict__ A, int lda,
                                              const float* __restrict__ B,
                                              float* __restrict__ Cpart,
                                              int M, int N) {
    __shared__ __align__(16) float As[KLEN][68];   // [k][m]
    __shared__ __align__(16) float Bs[KLEN][64];   // [k][n]
    int t  = threadIdx.x;
    int tx = t & 15, ty = t >> 4;
    int m0 = blockIdx.x * 64, n0 = blockIdx.y * 64;
    int kb = blockIdx.z * KLEN;

    // stage A slice: 64 rows x KLEN, 4 threads/row
    {
        int row = t >> 2, c0 = t & 3;
        const float* Ar = A + (size_t)(m0 + row) * lda + kb;
#pragma unroll
        for (int i = 0; i < KLEN / 16; i++) {
            int kq = (c0 + i * 4) * 4;
            float4 v = *(const float4*)(Ar + kq);
            As[kq + 0][row] = v.x;
            As[kq + 1][row] = v.y;
            As[kq + 2][row] = v.z;
            As[kq + 3][row] = v.w;
        }
    }
    // stage B slice: KLEN rows x 64
    {
        int kr = t >> 4, nq = (t & 15) * 4;
#pragma unroll
        for (int i = 0; i < KLEN / 16; i++) {
            int k = kr + i * 16;
            *(float4*)(&Bs[k][nq]) = *(const float4*)(B + (size_t)(kb + k) * N + n0 + nq);
        }
    }
    __syncthreads();

    ull acc[4][2] = {};
#pragma unroll 16
    for (int kk = 0; kk < KLEN; kk++) {
        float4 a = *(const float4*)(&As[kk][ty * 4]);
        ulonglong2 b = *(const ulonglong2*)(&Bs[kk][tx * 4]);
        float av[4] = {a.x, a.y, a.z, a.w};
#pragma unroll
        for (int i = 0; i < 4; i++) {
            ull ap = pk2(av[i], av[i]);
            acc[i][0] = fma2(ap, b.x, acc[i][0]);
            acc[i][1] = fma2(ap, b.y, acc[i][1]);
        }
    }

    float* Cp = Cpart + (size_t)blockIdx.z * M * N;
#pragma unroll
    for (int i = 0; i < 4; i++)
        *(ulonglong2*)(Cp + (size_t)(m0 + ty * 4 + i) * N + n0 + tx * 4) =
            make_ulonglong2(acc[i][0], acc[i][1]);
}

// ---------------- one-time setup ----------------
__global__ void build_wcat(const float* __restrict__ W_ih, const float* __restrict__ W_hh,
                           const float* __restrict__ b_ih, const float* __restrict__ b_hh) {
    int idx = blockIdx.x * 256 + threadIdx.x;
    if (idx < KPAD * HID) {
        int k = idx / HID, h = idx - k * HID;
        float w = 0.0f;
        if (k < 576)       w = W_ih[(size_t)h * 576 + k];
        else if (k < KCAT) w = W_hh[(size_t)h * 512 + (k - 576)];
        g_WcatT[idx] = w;
    }
    if (idx < HID) g_bsum[idx] = b_ih[idx] + b_hh[idx];
}

__global__ void init_state(const float* __restrict__ h0, const float* __restrict__ x0) {
    int i = blockIdx.x * 256 + threadIdx.x;
    if (i < BATCH * HID) g_h0buf[i] = h0[i];
    if (i < BATCH * OUTD) g_x0buf[i] = x0[i];
    if (i < BATCH * (KPAD - KCAT)) {
        int b = i / (KPAD - KCAT), c = i - b * (KPAD - KCAT);
        g_rin[b * KPAD + KCAT + c] = 0.0f;
    }
}

// ============== fused flash-style: q-reduce + score + online-softmax + ctx + pack ========
// grid 256 (one block per b), 512 threads (16 warps x 16 s-rows).
__global__ void __launch_bounds__(512, 2) scorectx(const float* __restrict__ v,
                                                   const float* __restrict__ enc,
                                                   const float* __restrict__ xin,
                                                   const float* __restrict__ hin) {
    __shared__ __align__(16) float sq[HID];
    __shared__ __align__(16) float sv[HID];
    __shared__ __align__(16) float ctxp[16][HID];
    __shared__ float wm[16], wl[16], walpha[16], sinvL;

    int b = blockIdx.x, t = threadIdx.x;
    int warp = t >> 5, lane = t & 31;

    {
        float s = 0.0f;
#pragma unroll
        for (int ks = 0; ks < KSPLIT; ks++)
            s += g_qpart[(size_t)ks * BATCH * HID + b * HID + t];
        sq[t] = s;
        sv[t] = v[t];
    }
    __syncthreads();

    const float4* q4 = (const float4*)sq;
    const float4* v4 = (const float4*)sv;

    ull c[8] = {};
    float m = -3.4e38f, l = 0.0f;

    for (int i = 0; i < 16; i++) {
        int s = warp * 16 + i;
        const float4*     Pr = (const float4*)(g_P + ((size_t)s * BATCH + b) * HID);
        const ulonglong2* Er = (const ulonglong2*)(enc + ((size_t)s * BATCH + b) * HID);
        float4 p0 = Pr[lane], p1 = Pr[32 + lane], p2 = Pr[64 + lane], p3 = Pr[96 + lane];
        ulonglong2 E0 = Er[lane], E1 = Er[32 + lane], E2 = Er[64 + lane], E3 = Er[96 + lane];
        float4 q0 = q4[lane], q1 = q4[32 + lane], q2 = q4[64 + lane], q3 = q4[96 + lane];
        float4 v0 = v4[lane], v1 = v4[32 + lane], v2 = v4[64 + lane], v3 = v4[96 + lane];

        float acc = fast_tanh(p0.x + q0.x) * v0.x + fast_tanh(p0.y + q0.y) * v0.y +
                    fast_tanh(p0.z + q0.z) * v0.z + fast_tanh(p0.w + q0.w) * v0.w;
        acc      += fast_tanh(p1.x + q1.x) * v1.x + fast_tanh(p1.y + q1.y) * v1.y +
                    fast_tanh(p1.z + q1.z) * v1.z + fast_tanh(p1.w + q1.w) * v1.w;
        acc      += fast_tanh(p2.x + q2.x) * v2.x + fast_tanh(p2.y + q2.y) * v2.y +
                    fast_tanh(p2.z + q2.z) * v2.z + fast_tanh(p2.w + q2.w) * v2.w;
        acc      += fast_tanh(p3.x + q3.x) * v3.x + fast_tanh(p3.y + q3.y) * v3.y +
                    fast_tanh(p3.z + q3.z) * v3.z + fast_tanh(p3.w + q3.w) * v3.w;
#pragma unroll
        for (int o = 16; o; o >>= 1) acc += __shfl_xor_sync(0xffffffffu, acc, o);

        float mnew = fmaxf(m, acc);
        float resc = __expf(m - mnew);
        float ws   = __expf(acc - mnew);
        l = l * resc + ws;
        ull r2 = pk2(resc, resc), w2 = pk2(ws, ws);
        c[0] = fma2(c[0], r2, mul2(E0.x, w2));
        c[1] = fma2(c[1], r2, mul2(E0.y, w2));
        c[2] = fma2(c[2], r2, mul2(E1.x, w2));
        c[3] = fma2(c[3], r2, mul2(E1.y, w2));
        c[4] = fma2(c[4], r2, mul2(E2.x, w2));
        c[5] = fma2(c[5], r2, mul2(E2.y, w2));
        c[6] = fma2(c[6], r2, mul2(E3.x, w2));
        c[7] = fma2(c[7], r2, mul2(E3.y, w2));
        m = mnew;
    }

    if (lane == 0) { wm[warp] = m; wl[warp] = l; }
    ulonglong2* cp = (ulonglong2*)ctxp[warp];
    cp[lane]      = make_ulonglong2(c[0], c[1]);
    cp[32 + lane] = make_ulonglong2(c[2], c[3]);
    cp[64 + lane] = make_ulonglong2(c[4], c[5]);
    cp[96 + lane] = make_ulonglong2(c[6], c[7]);
    __syncthreads();

    if (t < 16) {
        float mw = wm[t];
        float M = mw;
#pragma unroll
        for (int o = 8; o; o >>= 1) M = fmaxf(M, __shfl_xor_sync(0xffffu, M, o));
        float a = __expf(mw - M);
        float Lp = wl[t] * a;
#pragma unroll
        for (int o = 8; o; o >>= 1) Lp += __shfl_xor_sync(0xffffu, Lp, o);
        walpha[t] = a;
        if (t == 0) sinvL = __fdividef(1.0f, Lp);
    }
    __syncthreads();

    {
        float cc = 0.0f;
#pragma unroll
        for (int w = 0; w < 16; w++) cc += walpha[w] * ctxp[w][t];
        g_rin[b * KPAD + OUTD + t] = cc * sinvL;
        g_rin[b * KPAD + OUTD + HID + t] = hin[b * HID + t];
    }
    if (t < OUTD) g_rin[b * KPAD + t] = xin[b * OUTD + t];
}

// ============== reduce rnn partials + tanh + output head + argmax + one-hot ==============
__global__ void __launch_bounds__(256) outred(const float* __restrict__ Wo,
                                              const float* __restrict__ bo,
                                              float* __restrict__ hout,
                                              float* __restrict__ dout,
                                              float* __restrict__ xnext, int step) {
    int b = blockIdx.x, t = threadIdx.x;
    __shared__ __align__(16) float sh[HID];
    __shared__ float so[OUTD];
    __shared__ int sbest;

    float s0 = g_bsum[t], s1 = g_bsum[t + 256];
#pragma unroll
    for (int ks = 0; ks < KSPLITR; ks++) {
        const float* p = g_rnnpart + (size_t)ks * BATCH * HID + b * HID;
        s0 += p[t];
        s1 += p[t + 256];
    }
    float v0 = fast_tanh(s0), v1 = fast_tanh(s1);
    sh[t] = v0;
    sh[t + 256] = v1;
    hout[b * HID + t] = v0;
    hout[b * HID + t + 256] = v1;
    __syncthreads();

    int warp = t >> 5, lane = t & 31;
    const float4* h4 = (const float4*)sh;
    for (int o = warp; o < OUTD; o += 8) {
        const float4* w4 = (const float4*)(Wo + (size_t)o * HID);
        float acc = 0.0f;
#pragma unroll
        for (int i = 0; i < 4; i++) {
            float4 w = w4[i * 32 + lane], h = h4[i * 32 + lane];
            acc += w.x * h.x + w.y * h.y + w.z * h.z + w.w * h.w;
        }
#pragma unroll
        for (int off = 16; off; off >>= 1) acc += __shfl_xor_sync(0xffffffffu, acc, off);
        if (lane == 0) so[o] = acc + bo[o];
    }
    __syncthreads();
    if (t < OUTD) dout[((size_t)b * OUTD + t) * NSTEP + step] = so[t];
    if (t == 0) {
        float best = so[0];
        int bi = 0;
#pragma unroll
        for (int o = 1; o < OUTD; o++)
            if (so[o] > best) { best = so[o]; bi = o; }
        sbest = bi;
    }
    __syncthreads();
    if (t < OUTD) xnext[b * OUTD + t] = (t == sbest) ? 1.0f : 0.0f;
}

// ---------------- launch ----------------
extern "C" void kernel_launch(void* const* d_in, const int* in_sizes, int n_in,
                              void* d_out, int out_size) {
    const float* sos = (const float*)d_in[0];
    const float* h0  = (const float*)d_in[1];
    const float* enc = (const float*)d_in[2];
    const float* Wa  = (const float*)d_in[3];
    const float* ba  = (const float*)d_in[4];
    const float* v   = (const float*)d_in[5];
    const float* Wih = (const float*)d_in[6];
    const float* bih = (const float*)d_in[7];
    const float* Whh = (const float*)d_in[8];
    const float* bhh = (const float*)d_in[9];
    const float* Wo  = (const float*)d_in[10];
    const float* bo  = (const float*)d_in[11];
    float* out = (float*)d_out;

    float *pP, *pqp, *prp, *pr, *pW, *ph[2], *px[2];
    cudaGetSymbolAddress((void**)&pP,  g_P);
    cudaGetSymbolAddress((void**)&pqp, g_qpart);
    cudaGetSymbolAddress((void**)&prp, g_rnnpart);
    cudaGetSymbolAddress((void**)&pr,  g_rin);
    cudaGetSymbolAddress((void**)&pW,  g_WcatT);
    cudaGetSymbolAddress((void**)&ph[0], g_h0buf);
    cudaGetSymbolAddress((void**)&ph[1], g_h1buf);
    cudaGetSymbolAddress((void**)&px[0], g_x0buf);
    cudaGetSymbolAddress((void**)&px[1], g_x1buf);

    init_state<<<512, 256>>>(h0, sos);
    build_wcat<<<(KPAD * HID + 255) / 256, 256>>>(Wih, Whh, bih, bhh);
    gemm128<<<dim3(S_LEN * BATCH / 128, HID / 128), 256>>>(enc, Wa + 512 * HID, ba, pP,
                                                           S_LEN * BATCH, HID, HID);

    for (int t = 0; t < NSTEP; t++) {
        int cur = t & 1, nxt = cur ^ 1;
        // q partials = h_t @ Wa[:512], split-K 8x64
        gemmsk<64><<<dim3(BATCH / 64, HID / 64, KSPLIT), 256>>>(ph[cur], HID, Wa, pqp,
                                                                BATCH, HID);
        scorectx<<<BATCH, 512>>>(v, enc, px[cur], ph[cur]);
        // rnn partials = rnn_in @ WcatT, split-K 16x80 (padded)
        gemmsk<80><<<dim3(BATCH / 64, HID / 64, KSPLITR), 256>>>(pr, KPAD, pW, prp,
                                                                 BATCH, HID);
        outred<<<BATCH, 256>>>(Wo, bo, ph[nxt], out, px[nxt], t);
    }
}

// round 6
// speedup vs baseline: 1.1067x; 1.1067x over previous
#include <cuda_runtime.h>
#include <cstddef>

#define S_LEN   256
#define BATCH   256
#define HID     512
#define OUTD    64
#define NSTEP   63
#define KCAT    1088   // 64 (x) + 512 (ctx) + 512 (h)
#define KPAD    1152   // 8 splits * 144
#define KSPLIT  8

typedef unsigned long long ull;

// ---------------- scratch (device globals: allocation-free rule) ----------------
__device__ float g_P[(size_t)S_LEN * BATCH * HID];
__device__ float g_qpart[KSPLIT * BATCH * HID];
__device__ float g_rnnpart[KSPLIT * BATCH * HID];
__device__ float g_rin[BATCH * KPAD];                 // [x | ctx | h | 0-pad]
__device__ float g_WcatT[KPAD * HID];
__device__ float g_bsum[HID];
__device__ float g_h0buf[BATCH * HID];
__device__ float g_h1buf[BATCH * HID];
__device__ float g_x0buf[BATCH * OUTD];
__device__ float g_x1buf[BATCH * OUTD];

__device__ __forceinline__ float fast_tanh(float x) {
    float e = __expf(2.0f * x);
    return 1.0f - __fdividef(2.0f, e + 1.0f);
}

// ---- packed f32x2 helpers ----
__device__ __forceinline__ ull pk2(float lo, float hi) {
    ull r; asm("mov.b64 %0, {%1, %2};" : "=l"(r) : "f"(lo), "f"(hi)); return r;
}
__device__ __forceinline__ ull fma2(ull a, ull b, ull c) {
    ull d; asm("fma.rn.f32x2 %0, %1, %2, %3;" : "=l"(d) : "l"(a), "l"(b), "l"(c)); return d;
}

// ============== P precompute: 128x128 tile, 8x8 microtile, db + FFMA2 ==============
__global__ void __launch_bounds__(256) gemm128(const float* __restrict__ A,
                                               const float* __restrict__ B,
                                               const float* __restrict__ bias,
                                               float* __restrict__ C,
                                               int M, int N, int K) {
    __shared__ __align__(16) float As[2][8][132];
    __shared__ __align__(16) float Bs[2][8][128];
    int t  = threadIdx.x;
    int tx = t & 15, ty = t >> 4;
    int m0 = blockIdx.x * 128, n0 = blockIdx.y * 128;

    int ar = t >> 1, ak = (t & 1) * 4;
    int br = t >> 5, bn = (t & 31) * 4;

    const float* Aptr = A + (size_t)(m0 + ar) * K + ak;
    const float* Bptr = B + (size_t)br * N + n0 + bn;

    ull accp[8][4];
#pragma unroll
    for (int jp = 0; jp < 4; jp++) {
        int n = n0 + ((jp < 2) ? tx * 4 + jp * 2 : 64 + tx * 4 + (jp - 2) * 2);
        ull bv = bias ? pk2(bias[n], bias[n + 1]) : 0ull;
#pragma unroll
        for (int i = 0; i < 8; i++) accp[i][jp] = bv;
    }

    float4 a_reg = *(const float4*)(Aptr);
    float4 b_reg = *(const float4*)(Bptr);
    As[0][ak + 0][ar] = a_reg.x;
    As[0][ak + 1][ar] = a_reg.y;
    As[0][ak + 2][ar] = a_reg.z;
    As[0][ak + 3][ar] = a_reg.w;
    *(float4*)(&Bs[0][br][bn]) = b_reg;
    __syncthreads();

    int nc = K / 8, buf = 0;
    for (int c = 0; c < nc; c++) {
        if (c + 1 < nc) {
            a_reg = *(const float4*)(Aptr + (c + 1) * 8);
            b_reg = *(const float4*)(Bptr + (size_t)(c + 1) * 8 * N);
        }
#pragma unroll
        for (int kk = 0; kk < 8; kk++) {
            float4 a0 = *(const float4*)(&As[buf][kk][ty * 4]);
            float4 a1 = *(const float4*)(&As[buf][kk][64 + ty * 4]);
            ulonglong2 bq0 = *(const ulonglong2*)(&Bs[buf][kk][tx * 4]);
            ulonglong2 bq1 = *(const ulonglong2*)(&Bs[buf][kk][64 + tx * 4]);
            float av[8] = {a0.x, a0.y, a0.z, a0.w, a1.x, a1.y, a1.z, a1.w};
            ull bp[4] = {bq0.x, bq0.y, bq1.x, bq1.y};
#pragma unroll
            for (int i = 0; i < 8; i++) {
                ull ap = pk2(av[i], av[i]);
#pragma unroll
                for (int jp = 0; jp < 4; jp++) accp[i][jp] = fma2(ap, bp[jp], accp[i][jp]);
            }
        }
        if (c + 1 < nc) {
            int nb = buf ^ 1;
            As[nb][ak + 0][ar] = a_reg.x;
            As[nb][ak + 1][ar] = a_reg.y;
            As[nb][ak + 2][ar] = a_reg.z;
            As[nb][ak + 3][ar] = a_reg.w;
            *(float4*)(&Bs[nb][br][bn]) = b_reg;
        }
        __syncthreads();
        buf ^= 1;
    }

#pragma unroll
    for (int i = 0; i < 8; i++) {
        int m = m0 + ((i < 4) ? ty * 4 + i : 64 + ty * 4 + (i - 4));
        *(ulonglong2*)(C + (size_t)m * N + n0 + tx * 4)      = make_ulonglong2(accp[i][0], accp[i][1]);
        *(ulonglong2*)(C + (size_t)m * N + n0 + 64 + tx * 4) = make_ulonglong2(accp[i][2], accp[i][3]);
    }
}

// ============== q gemm: single-stage full-K-slice split-K (best measured) ==============
template <int KLEN>
__global__ void __launch_bounds__(256) gemmsk(const float* __restrict__ A, int lda,
                                              const float* __restrict__ B,
                                              float* __restrict__ Cpart,
                                              int M, int N) {
    __shared__ __align__(16) float As[KLEN][68];
    __shared__ __align__(16) float Bs[KLEN][64];
    int t  = threadIdx.x;
    int tx = t & 15, ty = t >> 4;
    int m0 = blockIdx.x * 64, n0 = blockIdx.y * 64;
    int kb = blockIdx.z * KLEN;

    {
        int row = t >> 2, c0 = t & 3;
        const float* Ar = A + (size_t)(m0 + row) * lda + kb;
#pragma unroll
        for (int i = 0; i < KLEN / 16; i++) {
            int kq = (c0 + i * 4) * 4;
            float4 v = *(const float4*)(Ar + kq);
            As[kq + 0][row] = v.x;
            As[kq + 1][row] = v.y;
            As[kq + 2][row] = v.z;
            As[kq + 3][row] = v.w;
        }
    }
    {
        int kr = t >> 4, nq = (t & 15) * 4;
#pragma unroll
        for (int i = 0; i < KLEN / 16; i++) {
            int k = kr + i * 16;
            *(float4*)(&Bs[k][nq]) = *(const float4*)(B + (size_t)(kb + k) * N + n0 + nq);
        }
    }
    __syncthreads();

    ull acc[4][2] = {};
#pragma unroll 16
    for (int kk = 0; kk < KLEN; kk++) {
        float4 a = *(const float4*)(&As[kk][ty * 4]);
        ulonglong2 b = *(const ulonglong2*)(&Bs[kk][tx * 4]);
        float av[4] = {a.x, a.y, a.z, a.w};
#pragma unroll
        for (int i = 0; i < 4; i++) {
            ull ap = pk2(av[i], av[i]);
            acc[i][0] = fma2(ap, b.x, acc[i][0]);
            acc[i][1] = fma2(ap, b.y, acc[i][1]);
        }
    }

    float* Cp = Cpart + (size_t)blockIdx.z * M * N;
#pragma unroll
    for (int i = 0; i < 4; i++)
        *(ulonglong2*)(Cp + (size_t)(m0 + ty * 4 + i) * N + n0 + tx * 4) =
            make_ulonglong2(acc[i][0], acc[i][1]);
}

// ============== rnn gemm: double-buffered 16-chunk split-K (R4 winner) + FFMA2 ==========
template <int KLEN>
__global__ void __launch_bounds__(256) gemm64s(const float* __restrict__ A, int lda,
                                               const float* __restrict__ B,
                                               float* __restrict__ Cpart,
                                               int M, int N) {
    __shared__ __align__(16) float As[2][16][68];
    __shared__ __align__(16) float Bs[2][16][64];
    constexpr int NC = KLEN / 16;
    int t  = threadIdx.x;
    int tx = t & 15, ty = t >> 4;
    int m0 = blockIdx.x * 64, n0 = blockIdx.y * 64;
    int kbase = blockIdx.z * KLEN;

    ull acc[4][2] = {};

    int arow = t >> 2, akq = (t & 3) * 4;
    int bk = t >> 4, bn = (t & 15) * 4;

    const float* Aptr = A + (size_t)(m0 + arow) * lda + kbase + akq;
    const float* Bptr = B + (size_t)(kbase + bk) * N + n0 + bn;

    float4 av = *(const float4*)(Aptr);
    float4 bv = *(const float4*)(Bptr);
    As[0][akq + 0][arow] = av.x;
    As[0][akq + 1][arow] = av.y;
    As[0][akq + 2][arow] = av.z;
    As[0][akq + 3][arow] = av.w;
    *(float4*)(&Bs[0][bk][bn]) = bv;
    __syncthreads();

    int buf = 0;
#pragma unroll
    for (int c = 0; c < NC; c++) {
        if (c + 1 < NC) {
            av = *(const float4*)(Aptr + (c + 1) * 16);
            bv = *(const float4*)(Bptr + (size_t)(c + 1) * 16 * N);
        }
#pragma unroll
        for (int kk = 0; kk < 16; kk++) {
            float4 a = *(const float4*)(&As[buf][kk][ty * 4]);
            ulonglong2 b = *(const ulonglong2*)(&Bs[buf][kk][tx * 4]);
            float aa[4] = {a.x, a.y, a.z, a.w};
#pragma unroll
            for (int i = 0; i < 4; i++) {
                ull ap = pk2(aa[i], aa[i]);
                acc[i][0] = fma2(ap, b.x, acc[i][0]);
                acc[i][1] = fma2(ap, b.y, acc[i][1]);
            }
        }
        if (c + 1 < NC) {
            int nb = buf ^ 1;
            As[nb][akq + 0][arow] = av.x;
            As[nb][akq + 1][arow] = av.y;
            As[nb][akq + 2][arow] = av.z;
            As[nb][akq + 3][arow] = av.w;
            *(float4*)(&Bs[nb][bk][bn]) = bv;
        }
        __syncthreads();
        buf ^= 1;
    }

    float* Cp = Cpart + (size_t)blockIdx.z * M * N;
#pragma unroll
    for (int i = 0; i < 4; i++)
        *(ulonglong2*)(Cp + (size_t)(m0 + ty * 4 + i) * N + n0 + tx * 4) =
            make_ulonglong2(acc[i][0], acc[i][1]);
}

// ---------------- one-time setup ----------------
__global__ void build_wcat(const float* __restrict__ W_ih, const float* __restrict__ W_hh,
                           const float* __restrict__ b_ih, const float* __restrict__ b_hh) {
    int idx = blockIdx.x * 256 + threadIdx.x;
    if (idx < KPAD * HID) {
        int k = idx / HID, h = idx - k * HID;
        float w = 0.0f;
        if (k < 576)       w = W_ih[(size_t)h * 576 + k];
        else if (k < KCAT) w = W_hh[(size_t)h * 512 + (k - 576)];
        g_WcatT[idx] = w;
    }
    if (idx < HID) g_bsum[idx] = b_ih[idx] + b_hh[idx];
}

__global__ void init_state(const float* __restrict__ h0, const float* __restrict__ x0) {
    int i = blockIdx.x * 256 + threadIdx.x;
    if (i < BATCH * HID) g_h0buf[i] = h0[i];
    if (i < BATCH * OUTD) g_x0buf[i] = x0[i];
    if (i < BATCH * (KPAD - KCAT)) {
        int b = i / (KPAD - KCAT), c = i - b * (KPAD - KCAT);
        g_rin[b * KPAD + KCAT + c] = 0.0f;
    }
}

// ============== fused: q-reduce + score + DIRECT softmax (no max) + ctx + pack ==========
// Scores are bounded: |score| <= sum|v| ~ 20, exp safe in fp32. Softmax is
// shift-invariant, so exp(s)/sum(exp(s)) == reference exactly up to rounding.
// grid 256 (one block per b), 512 threads (16 warps x 16 s-rows).
__global__ void __launch_bounds__(512, 2) scorectx(const float* __restrict__ v,
                                                   const float* __restrict__ enc,
                                                   const float* __restrict__ xin,
                                                   const float* __restrict__ hin) {
    __shared__ __align__(16) float sq[HID];
    __shared__ __align__(16) float sv[HID];
    __shared__ __align__(16) float ctxp[16][HID];
    __shared__ float wl[16];
    __shared__ float sinvL;

    int b = blockIdx.x, t = threadIdx.x;
    int warp = t >> 5, lane = t & 31;

    {
        float s = 0.0f;
#pragma unroll
        for (int ks = 0; ks < KSPLIT; ks++)
            s += g_qpart[(size_t)ks * BATCH * HID + b * HID + t];
        sq[t] = s;
        sv[t] = v[t];
    }
    __syncthreads();

    const float4* q4 = (const float4*)sq;
    const float4* v4 = (const float4*)sv;

    ull c[8] = {};
    float l = 0.0f;

    for (int i = 0; i < 16; i++) {
        int s = warp * 16 + i;
        const float4*     Pr = (const float4*)(g_P + ((size_t)s * BATCH + b) * HID);
        const ulonglong2* Er = (const ulonglong2*)(enc + ((size_t)s * BATCH + b) * HID);
        float4 p0 = Pr[lane], p1 = Pr[32 + lane], p2 = Pr[64 + lane], p3 = Pr[96 + lane];
        ulonglong2 E0 = Er[lane], E1 = Er[32 + lane], E2 = Er[64 + lane], E3 = Er[96 + lane];
        float4 q0 = q4[lane], q1 = q4[32 + lane], q2 = q4[64 + lane], q3 = q4[96 + lane];
        float4 v0 = v4[lane], v1 = v4[32 + lane], v2 = v4[64 + lane], v3 = v4[96 + lane];

        float acc = fast_tanh(p0.x + q0.x) * v0.x + fast_tanh(p0.y + q0.y) * v0.y +
                    fast_tanh(p0.z + q0.z) * v0.z + fast_tanh(p0.w + q0.w) * v0.w;
        acc      += fast_tanh(p1.x + q1.x) * v1.x + fast_tanh(p1.y + q1.y) * v1.y +
                    fast_tanh(p1.z + q1.z) * v1.z + fast_tanh(p1.w + q1.w) * v1.w;
        acc      += fast_tanh(p2.x + q2.x) * v2.x + fast_tanh(p2.y + q2.y) * v2.y +
                    fast_tanh(p2.z + q2.z) * v2.z + fast_tanh(p2.w + q2.w) * v2.w;
        acc      += fast_tanh(p3.x + q3.x) * v3.x + fast_tanh(p3.y + q3.y) * v3.y +
                    fast_tanh(p3.z + q3.z) * v3.z + fast_tanh(p3.w + q3.w) * v3.w;
#pragma unroll
        for (int o = 16; o; o >>= 1) acc += __shfl_xor_sync(0xffffffffu, acc, o);

        float w = __expf(acc);      // no max subtraction needed: |acc| bounded
        l += w;
        ull w2 = pk2(w, w);
        c[0] = fma2(E0.x, w2, c[0]);
        c[1] = fma2(E0.y, w2, c[1]);
        c[2] = fma2(E1.x, w2, c[2]);
        c[3] = fma2(E1.y, w2, c[3]);
        c[4] = fma2(E2.x, w2, c[4]);
        c[5] = fma2(E2.y, w2, c[5]);
        c[6] = fma2(E3.x, w2, c[6]);
        c[7] = fma2(E3.y, w2, c[7]);
    }

    if (lane == 0) wl[warp] = l;
    ulonglong2* cp = (ulonglong2*)ctxp[warp];
    cp[lane]      = make_ulonglong2(c[0], c[1]);
    cp[32 + lane] = make_ulonglong2(c[2], c[3]);
    cp[64 + lane] = make_ulonglong2(c[4], c[5]);
    cp[96 + lane] = make_ulonglong2(c[6], c[7]);
    __syncthreads();

    if (t < 16) {
        float Lp = wl[t];
#pragma unroll
        for (int o = 8; o; o >>= 1) Lp += __shfl_xor_sync(0xffffu, Lp, o);
        if (t == 0) sinvL = __fdividef(1.0f, Lp);
    }
    __syncthreads();

    {
        float cc = 0.0f;
#pragma unroll
        for (int w = 0; w < 16; w++) cc += ctxp[w][t];
        g_rin[b * KPAD + OUTD + t] = cc * sinvL;
        g_rin[b * KPAD + OUTD + HID + t] = hin[b * HID + t];
    }
    if (t < OUTD) g_rin[b * KPAD + t] = xin[b * OUTD + t];
}

// ============== reduce rnn partials + tanh + output head + argmax + one-hot ==============
__global__ void __launch_bounds__(256) outred(const float* __restrict__ Wo,
                                              const float* __restrict__ bo,
                                              float* __restrict__ hout,
                                              float* __restrict__ dout,
                                              float* __restrict__ xnext, int step) {
    int b = blockIdx.x, t = threadIdx.x;
    __shared__ __align__(16) float sh[HID];
    __shared__ float so[OUTD];
    __shared__ int sbest;

    float s0 = g_bsum[t], s1 = g_bsum[t + 256];
#pragma unroll
    for (int ks = 0; ks < KSPLIT; ks++) {
        const float* p = g_rnnpart + (size_t)ks * BATCH * HID + b * HID;
        s0 += p[t];
        s1 += p[t + 256];
    }
    float v0 = fast_tanh(s0), v1 = fast_tanh(s1);
    sh[t] = v0;
    sh[t + 256] = v1;
    hout[b * HID + t] = v0;
    hout[b * HID + t + 256] = v1;
    __syncthreads();

    int warp = t >> 5, lane = t & 31;
    const float4* h4 = (const float4*)sh;
    for (int o = warp; o < OUTD; o += 8) {
        const float4* w4 = (const float4*)(Wo + (size_t)o * HID);
        float acc = 0.0f;
#pragma unroll
        for (int i = 0; i < 4; i++) {
            float4 w = w4[i * 32 + lane], h = h4[i * 32 + lane];
            acc += w.x * h.x + w.y * h.y + w.z * h.z + w.w * h.w;
        }
#pragma unroll
        for (int off = 16; off; off >>= 1) acc += __shfl_xor_sync(0xffffffffu, acc, off);
        if (lane == 0) so[o] = acc + bo[o];
    }
    __syncthreads();
    if (t < OUTD) dout[((size_t)b * OUTD + t) * NSTEP + step] = so[t];
    if (t == 0) {
        float best = so[0];
        int bi = 0;
#pragma unroll
        for (int o = 1; o < OUTD; o++)
            if (so[o] > best) { best = so[o]; bi = o; }
        sbest = bi;
    }
    __syncthreads();
    if (t < OUTD) xnext[b * OUTD + t] = (t == sbest) ? 1.0f : 0.0f;
}

// ---------------- launch ----------------
extern "C" void kernel_launch(void* const* d_in, const int* in_sizes, int n_in,
                              void* d_out, int out_size) {
    const float* sos = (const float*)d_in[0];
    const float* h0  = (const float*)d_in[1];
    const float* enc = (const float*)d_in[2];
    const float* Wa  = (const float*)d_in[3];
    const float* ba  = (const float*)d_in[4];
    const float* v   = (const float*)d_in[5];
    const float* Wih = (const float*)d_in[6];
    const float* bih = (const float*)d_in[7];
    const float* Whh = (const float*)d_in[8];
    const float* bhh = (const float*)d_in[9];
    const float* Wo  = (const float*)d_in[10];
    const float* bo  = (const float*)d_in[11];
    float* out = (float*)d_out;

    float *pP, *pqp, *prp, *pr, *pW, *ph[2], *px[2];
    cudaGetSymbolAddress((void**)&pP,  g_P);
    cudaGetSymbolAddress((void**)&pqp, g_qpart);
    cudaGetSymbolAddress((void**)&prp, g_rnnpart);
    cudaGetSymbolAddress((void**)&pr,  g_rin);
    cudaGetSymbolAddress((void**)&pW,  g_WcatT);
    cudaGetSymbolAddress((void**)&ph[0], g_h0buf);
    cudaGetSymbolAddress((void**)&ph[1], g_h1buf);
    cudaGetSymbolAddress((void**)&px[0], g_x0buf);
    cudaGetSymbolAddress((void**)&px[1], g_x1buf);

    init_state<<<512, 256>>>(h0, sos);
    build_wcat<<<(KPAD * HID + 255) / 256, 256>>>(Wih, Whh, bih, bhh);
    gemm128<<<dim3(S_LEN * BATCH / 128, HID / 128), 256>>>(enc, Wa + 512 * HID, ba, pP,
                                                           S_LEN * BATCH, HID, HID);

    for (int t = 0; t < NSTEP; t++) {
        int cur = t & 1, nxt = cur ^ 1;
        // q partials = h_t @ Wa[:512], split-K 8x64
        gemmsk<64><<<dim3(BATCH / 64, HID / 64, KSPLIT), 256>>>(ph[cur], HID, Wa, pqp,
                                                                BATCH, HID);
        scorectx<<<BATCH, 512>>>(v, enc, px[cur], ph[cur]);
        // rnn partials = rnn_in @ WcatT, split-K 8x144 (padded), double-buffered
        gemm64s<144><<<dim3(BATCH / 64, HID / 64, KSPLIT), 256>>>(pr, KPAD, pW, prp,
                                                                  BATCH, HID);
        outred<<<BATCH, 256>>>(Wo, bo, ph[nxt], out, px[nxt], t);
    }
}

// round 8
// speedup vs baseline: 1.2588x; 1.1375x over previous
#include <cuda_runtime.h>
#include <cstddef>

#define S_LEN    256
#define BATCH    256
#define HID      512
#define OUTD     64
#define NSTEP    63
#define KCAT     1088   // 64 (x) + 512 (ctx) + 512 (h)
#define KPAD     1152   // 8 splits * 144
#define KSPLIT   8      // rnn gemm split
#define KSPLIT_Q 16     // q gemm split (klen 32)

typedef unsigned long long ull;

// ---------------- scratch (device globals: allocation-free rule) ----------------
__device__ float g_P[(size_t)S_LEN * BATCH * HID];
__device__ float g_qpart[KSPLIT_Q * BATCH * HID];
__device__ float g_rnnpart[KSPLIT * BATCH * HID];
__device__ float g_rin[BATCH * KPAD];                 // [x | ctx | h | 0-pad]
__device__ float g_WcatT[KPAD * HID];
__device__ float g_bsum[HID];
__device__ float g_h0buf[BATCH * HID];
__device__ float g_h1buf[BATCH * HID];
__device__ float g_x0buf[BATCH * OUTD];
__device__ float g_x1buf[BATCH * OUTD];

__device__ __forceinline__ float fast_tanh(float x) {
    float e = __expf(2.0f * x);
    return 1.0f - __fdividef(2.0f, e + 1.0f);
}

// ---- packed f32x2 helpers ----
__device__ __forceinline__ ull pk2(float lo, float hi) {
    ull r; asm("mov.b64 %0, {%1, %2};" : "=l"(r) : "f"(lo), "f"(hi)); return r;
}
__device__ __forceinline__ ull fma2(ull a, ull b, ull c) {
    ull d; asm("fma.rn.f32x2 %0, %1, %2, %3;" : "=l"(d) : "l"(a), "l"(b), "l"(c)); return d;
}

// ============== P precompute: 128x128 tile, 8x8 microtile, db + FFMA2 ==============
__global__ void __launch_bounds__(256) gemm128(const float* __restrict__ A,
                                               const float* __restrict__ B,
                                               const float* __restrict__ bias,
                                               float* __restrict__ C,
                                               int M, int N, int K) {
    __shared__ __align__(16) float As[2][8][132];
    __shared__ __align__(16) float Bs[2][8][128];
    int t  = threadIdx.x;
    int tx = t & 15, ty = t >> 4;
    int m0 = blockIdx.x * 128, n0 = blockIdx.y * 128;

    int ar = t >> 1, ak = (t & 1) * 4;
    int br = t >> 5, bn = (t & 31) * 4;

    const float* Aptr = A + (size_t)(m0 + ar) * K + ak;
    const float* Bptr = B + (size_t)br * N + n0 + bn;

    ull accp[8][4];
#pragma unroll
    for (int jp = 0; jp < 4; jp++) {
        int n = n0 + ((jp < 2) ? tx * 4 + jp * 2 : 64 + tx * 4 + (jp - 2) * 2);
        ull bv = bias ? pk2(bias[n], bias[n + 1]) : 0ull;
#pragma unroll
        for (int i = 0; i < 8; i++) accp[i][jp] = bv;
    }

    float4 a_reg = *(const float4*)(Aptr);
    float4 b_reg = *(const float4*)(Bptr);
    As[0][ak + 0][ar] = a_reg.x;
    As[0][ak + 1][ar] = a_reg.y;
    As[0][ak + 2][ar] = a_reg.z;
    As[0][ak + 3][ar] = a_reg.w;
    *(float4*)(&Bs[0][br][bn]) = b_reg;
    __syncthreads();

    int nc = K / 8, buf = 0;
    for (int c = 0; c < nc; c++) {
        if (c + 1 < nc) {
            a_reg = *(const float4*)(Aptr + (c + 1) * 8);
            b_reg = *(const float4*)(Bptr + (size_t)(c + 1) * 8 * N);
        }
#pragma unroll
        for (int kk = 0; kk < 8; kk++) {
            float4 a0 = *(const float4*)(&As[buf][kk][ty * 4]);
            float4 a1 = *(const float4*)(&As[buf][kk][64 + ty * 4]);
            ulonglong2 bq0 = *(const ulonglong2*)(&Bs[buf][kk][tx * 4]);
            ulonglong2 bq1 = *(const ulonglong2*)(&Bs[buf][kk][64 + tx * 4]);
            float av[8] = {a0.x, a0.y, a0.z, a0.w, a1.x, a1.y, a1.z, a1.w};
            ull bp[4] = {bq0.x, bq0.y, bq1.x, bq1.y};
#pragma unroll
            for (int i = 0; i < 8; i++) {
                ull ap = pk2(av[i], av[i]);
#pragma unroll
                for (int jp = 0; jp < 4; jp++) accp[i][jp] = fma2(ap, bp[jp], accp[i][jp]);
            }
        }
        if (c + 1 < nc) {
            int nb = buf ^ 1;
            As[nb][ak + 0][ar] = a_reg.x;
            As[nb][ak + 1][ar] = a_reg.y;
            As[nb][ak + 2][ar] = a_reg.z;
            As[nb][ak + 3][ar] = a_reg.w;
            *(float4*)(&Bs[nb][br][bn]) = b_reg;
        }
        __syncthreads();
        buf ^= 1;
    }

#pragma unroll
    for (int i = 0; i < 8; i++) {
        int m = m0 + ((i < 4) ? ty * 4 + i : 64 + ty * 4 + (i - 4));
        *(ulonglong2*)(C + (size_t)m * N + n0 + tx * 4)      = make_ulonglong2(accp[i][0], accp[i][1]);
        *(ulonglong2*)(C + (size_t)m * N + n0 + 64 + tx * 4) = make_ulonglong2(accp[i][2], accp[i][3]);
    }
}

// ============== q gemm: single-stage full-K-slice split-K ==============
template <int KLEN>
__global__ void __launch_bounds__(256) gemmsk(const float* __restrict__ A, int lda,
                                              const float* __restrict__ B,
                                              float* __restrict__ Cpart,
                                              int M, int N) {
    __shared__ __align__(16) float As[KLEN][68];
    __shared__ __align__(16) float Bs[KLEN][64];
    int t  = threadIdx.x;
    int tx = t & 15, ty = t >> 4;
    int m0 = blockIdx.x * 64, n0 = blockIdx.y * 64;
    int kb = blockIdx.z * KLEN;

    {
        int row = t >> 2, c0 = t & 3;
        const float* Ar = A + (size_t)(m0 + row) * lda + kb;
#pragma unroll
        for (int i = 0; i < KLEN / 16; i++) {
            int kq = (c0 + i * 4) * 4;
            float4 v = *(const float4*)(Ar + kq);
            As[kq + 0][row] = v.x;
            As[kq + 1][row] = v.y;
            As[kq + 2][row] = v.z;
            As[kq + 3][row] = v.w;
        }
    }
    {
        int kr = t >> 4, nq = (t & 15) * 4;
#pragma unroll
        for (int i = 0; i < KLEN / 16; i++) {
            int k = kr + i * 16;
            *(float4*)(&Bs[k][nq]) = *(const float4*)(B + (size_t)(kb + k) * N + n0 + nq);
        }
    }
    __syncthreads();

    ull acc[4][2] = {};
#pragma unroll 16
    for (int kk = 0; kk < KLEN; kk++) {
        float4 a = *(const float4*)(&As[kk][ty * 4]);
        ulonglong2 b = *(const ulonglong2*)(&Bs[kk][tx * 4]);
        float av[4] = {a.x, a.y, a.z, a.w};
#pragma unroll
        for (int i = 0; i < 4; i++) {
            ull ap = pk2(av[i], av[i]);
            acc[i][0] = fma2(ap, b.x, acc[i][0]);
            acc[i][1] = fma2(ap, b.y, acc[i][1]);
        }
    }

    float* Cp = Cpart + (size_t)blockIdx.z * M * N;
#pragma unroll
    for (int i = 0; i < 4; i++)
        *(ulonglong2*)(Cp + (size_t)(m0 + ty * 4 + i) * N + n0 + tx * 4) =
            make_ulonglong2(acc[i][0], acc[i][1]);
}

// ============== rnn gemm: double-buffered 16-chunk split-K + FFMA2 ==============
template <int KLEN>
__global__ void __launch_bounds__(256) gemm64s(const float* __restrict__ A, int lda,
                                               const float* __restrict__ B,
                                               float* __restrict__ Cpart,
                                               int M, int N) {
    __shared__ __align__(16) float As[2][16][68];
    __shared__ __align__(16) float Bs[2][16][64];
    constexpr int NC = KLEN / 16;
    int t  = threadIdx.x;
    int tx = t & 15, ty = t >> 4;
    int m0 = blockIdx.x * 64, n0 = blockIdx.y * 64;
    int kbase = blockIdx.z * KLEN;

    ull acc[4][2] = {};

    int arow = t >> 2, akq = (t & 3) * 4;
    int bk = t >> 4, bn = (t & 15) * 4;

    const float* Aptr = A + (size_t)(m0 + arow) * lda + kbase + akq;
    const float* Bptr = B + (size_t)(kbase + bk) * N + n0 + bn;

    float4 av = *(const float4*)(Aptr);
    float4 bv = *(const float4*)(Bptr);
    As[0][akq + 0][arow] = av.x;
    As[0][akq + 1][arow] = av.y;
    As[0][akq + 2][arow] = av.z;
    As[0][akq + 3][arow] = av.w;
    *(float4*)(&Bs[0][bk][bn]) = bv;
    __syncthreads();

    int buf = 0;
#pragma unroll
    for (int c = 0; c < NC; c++) {
        if (c + 1 < NC) {
            av = *(const float4*)(Aptr + (c + 1) * 16);
            bv = *(const float4*)(Bptr + (size_t)(c + 1) * 16 * N);
        }
#pragma unroll
        for (int kk = 0; kk < 16; kk++) {
            float4 a = *(const float4*)(&As[buf][kk][ty * 4]);
            ulonglong2 b = *(const ulonglong2*)(&Bs[buf][kk][tx * 4]);
            float aa[4] = {a.x, a.y, a.z, a.w};
#pragma unroll
            for (int i = 0; i < 4; i++) {
                ull ap = pk2(aa[i], aa[i]);
                acc[i][0] = fma2(ap, b.x, acc[i][0]);
                acc[i][1] = fma2(ap, b.y, acc[i][1]);
            }
        }
        if (c + 1 < NC) {
            int nb = buf ^ 1;
            As[nb][akq + 0][arow] = av.x;
            As[nb][akq + 1][arow] = av.y;
            As[nb][akq + 2][arow] = av.z;
            As[nb][akq + 3][arow] = av.w;
            *(float4*)(&Bs[nb][bk][bn]) = bv;
        }
        __syncthreads();
        buf ^= 1;
    }

    float* Cp = Cpart + (size_t)blockIdx.z * M * N;
#pragma unroll
    for (int i = 0; i < 4; i++)
        *(ulonglong2*)(Cp + (size_t)(m0 + ty * 4 + i) * N + n0 + tx * 4) =
            make_ulonglong2(acc[i][0], acc[i][1]);
}

// ---------------- one-time setup ----------------
__global__ void build_wcat(const float* __restrict__ W_ih, const float* __restrict__ W_hh,
                           const float* __restrict__ b_ih, const float* __restrict__ b_hh) {
    int idx = blockIdx.x * 256 + threadIdx.x;
    if (idx < KPAD * HID) {
        int k = idx / HID, h = idx - k * HID;
        float w = 0.0f;
        if (k < 576)       w = W_ih[(size_t)h * 576 + k];
        else if (k < KCAT) w = W_hh[(size_t)h * 512 + (k - 576)];
        g_WcatT[idx] = w;
    }
    if (idx < HID) g_bsum[idx] = b_ih[idx] + b_hh[idx];
}

__global__ void init_state(const float* __restrict__ h0, const float* __restrict__ x0) {
    int i = blockIdx.x * 256 + threadIdx.x;
    if (i < BATCH * HID) g_h0buf[i] = h0[i];
    if (i < BATCH * OUTD) g_x0buf[i] = x0[i];
    if (i < BATCH * (KPAD - KCAT)) {
        int b = i / (KPAD - KCAT), c = i - b * (KPAD - KCAT);
        g_rin[b * KPAD + KCAT + c] = 0.0f;
    }
}

// ============== fused: q-reduce + score + direct softmax + ctx + pack ==============
// grid 256 (one block per b), 512 threads (16 warps x 16 s-rows).
__global__ void __launch_bounds__(512, 2) scorectx(const float* __restrict__ v,
                                                   const float* __restrict__ enc,
                                                   const float* __restrict__ xin,
                                                   const float* __restrict__ hin) {
    __shared__ __align__(16) float sq[HID];
    __shared__ __align__(16) float sv[HID];
    __shared__ __align__(16) float ctxp[16][HID];
    __shared__ float wl[16];
    __shared__ float sinvL;

    int b = blockIdx.x, t = threadIdx.x;
    int warp = t >> 5, lane = t & 31;

    {
        float s = 0.0f;
#pragma unroll
        for (int ks = 0; ks < KSPLIT_Q; ks++)
            s += g_qpart[(size_t)ks * BATCH * HID + b * HID + t];
        sq[t] = s;
        sv[t] = v[t];
    }
    __syncthreads();

    const float4* q4 = (const float4*)sq;
    const float4* v4 = (const float4*)sv;

    ull c[8] = {};
    float l = 0.0f;

#pragma unroll 2
    for (int i = 0; i < 16; i++) {
        int s = warp * 16 + i;
        const float4*     Pr = (const float4*)(g_P + ((size_t)s * BATCH + b) * HID);
        const ulonglong2* Er = (const ulonglong2*)(enc + ((size_t)s * BATCH + b) * HID);
        float4 p0 = Pr[lane], p1 = Pr[32 + lane], p2 = Pr[64 + lane], p3 = Pr[96 + lane];
        ulonglong2 E0 = Er[lane], E1 = Er[32 + lane], E2 = Er[64 + lane], E3 = Er[96 + lane];
        float4 q0 = q4[lane], q1 = q4[32 + lane], q2 = q4[64 + lane], q3 = q4[96 + lane];
        float4 v0 = v4[lane], v1 = v4[32 + lane], v2 = v4[64 + lane], v3 = v4[96 + lane];

        float acc = fast_tanh(p0.x + q0.x) * v0.x + fast_tanh(p0.y + q0.y) * v0.y +
                    fast_tanh(p0.z + q0.z) * v0.z + fast_tanh(p0.w + q0.w) * v0.w;
        acc      += fast_tanh(p1.x + q1.x) * v1.x + fast_tanh(p1.y + q1.y) * v1.y +
                    fast_tanh(p1.z + q1.z) * v1.z + fast_tanh(p1.w + q1.w) * v1.w;
        acc      += fast_tanh(p2.x + q2.x) * v2.x + fast_tanh(p2.y + q2.y) * v2.y +
                    fast_tanh(p2.z + q2.z) * v2.z + fast_tanh(p2.w + q2.w) * v2.w;
        acc      += fast_tanh(p3.x + q3.x) * v3.x + fast_tanh(p3.y + q3.y) * v3.y +
                    fast_tanh(p3.z + q3.z) * v3.z + fast_tanh(p3.w + q3.w) * v3.w;
#pragma unroll
        for (int o = 16; o; o >>= 1) acc += __shfl_xor_sync(0xffffffffu, acc, o);

        float w = __expf(acc);      // bounded scores: no max subtraction needed
        l += w;
        ull w2 = pk2(w, w);
        c[0] = fma2(E0.x, w2, c[0]);
        c[1] = fma2(E0.y, w2, c[1]);
        c[2] = fma2(E1.x, w2, c[2]);
        c[3] = fma2(E1.y, w2, c[3]);
        c[4] = fma2(E2.x, w2, c[4]);
        c[5] = fma2(E2.y, w2, c[5]);
        c[6] = fma2(E3.x, w2, c[6]);
        c[7] = fma2(E3.y, w2, c[7]);
    }

    if (lane == 0) wl[warp] = l;
    ulonglong2* cp = (ulonglong2*)ctxp[warp];
    cp[lane]      = make_ulonglong2(c[0], c[1]);
    cp[32 + lane] = make_ulonglong2(c[2], c[3]);
    cp[64 + lane] = make_ulonglong2(c[4], c[5]);
    cp[96 + lane] = make_ulonglong2(c[6], c[7]);
    __syncthreads();

    if (t < 16) {
        float Lp = wl[t];
#pragma unroll
        for (int o = 8; o; o >>= 1) Lp += __shfl_xor_sync(0xffffu, Lp, o);
        if (t == 0) sinvL = __fdividef(1.0f, Lp);
    }
    __syncthreads();

    {
        float cc = 0.0f;
#pragma unroll
        for (int w = 0; w < 16; w++) cc += ctxp[w][t];
        g_rin[b * KPAD + OUTD + t] = cc * sinvL;
        g_rin[b * KPAD + OUTD + HID + t] = hin[b * HID + t];
    }
    if (t < OUTD) g_rin[b * KPAD + t] = xin[b * OUTD + t];
}

// ============== reduce rnn partials + tanh + output head + argmax + one-hot ==============
__global__ void __launch_bounds__(256) outred(const float* __restrict__ Wo,
                                              const float* __restrict__ bo,
                                              float* __restrict__ hout,
                                              float* __restrict__ dout,
                                              float* __restrict__ xnext, int step) {
    int b = blockIdx.x, t = threadIdx.x;
    __shared__ __align__(16) float sh[HID];
    __shared__ float so[OUTD];
    __shared__ int sbest;

    float s0 = g_bsum[t], s1 = g_bsum[t + 256];
#pragma unroll
    for (int ks = 0; ks < KSPLIT; ks++) {
        const float* p = g_rnnpart + (size_t)ks * BATCH * HID + b * HID;
        s0 += p[t];
        s1 += p[t + 256];
    }
    float v0 = fast_tanh(s0), v1 = fast_tanh(s1);
    sh[t] = v0;
    sh[t + 256] = v1;
    hout[b * HID + t] = v0;
    hout[b * HID + t + 256] = v1;
    __syncthreads();

    int warp = t >> 5, lane = t & 31;
    const float4* h4 = (const float4*)sh;
    for (int o = warp; o < OUTD; o += 8) {
        const float4* w4 = (const float4*)(Wo + (size_t)o * HID);
        float acc = 0.0f;
#pragma unroll
        for (int i = 0; i < 4; i++) {
            float4 w = w4[i * 32 + lane], h = h4[i * 32 + lane];
            acc += w.x * h.x + w.y * h.y + w.z * h.z + w.w * h.w;
        }
#pragma unroll
        for (int off = 16; off; off >>= 1) acc += __shfl_xor_sync(0xffffffffu, acc, off);
        if (lane == 0) so[o] = acc + bo[o];
    }
    __syncthreads();
    if (t < OUTD) dout[((size_t)b * OUTD + t) * NSTEP + step] = so[t];
    if (t == 0) {
        float best = so[0];
        int bi = 0;
#pragma unroll
        for (int o = 1; o < OUTD; o++)
            if (so[o] > best) { best = so[o]; bi = o; }
        sbest = bi;
    }
    __syncthreads();
    if (t < OUTD) xnext[b * OUTD + t] = (t == sbest) ? 1.0f : 0.0f;
}

// ---------------- launch ----------------
extern "C" void kernel_launch(void* const* d_in, const int* in_sizes, int n_in,
                              void* d_out, int out_size) {
    const float* sos = (const float*)d_in[0];
    const float* h0  = (const float*)d_in[1];
    const float* enc = (const float*)d_in[2];
    const float* Wa  = (const float*)d_in[3];
    const float* ba  = (const float*)d_in[4];
    const float* v   = (const float*)d_in[5];
    const float* Wih = (const float*)d_in[6];
    const float* bih = (const float*)d_in[7];
    const float* Whh = (const float*)d_in[8];
    const float* bhh = (const float*)d_in[9];
    const float* Wo  = (const float*)d_in[10];
    const float* bo  = (const float*)d_in[11];
    float* out = (float*)d_out;

    float *pP, *pqp, *prp, *pr, *pW, *ph[2], *px[2];
    cudaGetSymbolAddress((void**)&pP,  g_P);
    cudaGetSymbolAddress((void**)&pqp, g_qpart);
    cudaGetSymbolAddress((void**)&prp, g_rnnpart);
    cudaGetSymbolAddress((void**)&pr,  g_rin);
    cudaGetSymbolAddress((void**)&pW,  g_WcatT);
    cudaGetSymbolAddress((void**)&ph[0], g_h0buf);
    cudaGetSymbolAddress((void**)&ph[1], g_h1buf);
    cudaGetSymbolAddress((void**)&px[0], g_x0buf);
    cudaGetSymbolAddress((void**)&px[1], g_x1buf);

    init_state<<<512, 256>>>(h0, sos);
    build_wcat<<<(KPAD * HID + 255) / 256, 256>>>(Wih, Whh, bih, bhh);
    gemm128<<<dim3(S_LEN * BATCH / 128, HID / 128), 256>>>(enc, Wa + 512 * HID, ba, pP,
                                                           S_LEN * BATCH, HID, HID);

    for (int t = 0; t < NSTEP; t++) {
        int cur = t & 1, nxt = cur ^ 1;
        // q partials = h_t @ Wa[:512], split-K 16x32
        gemmsk<32><<<dim3(BATCH / 64, HID / 64, KSPLIT_Q), 256>>>(ph[cur], HID, Wa, pqp,
                                                                  BATCH, HID);
        scorectx<<<BATCH, 512>>>(v, enc, px[cur], ph[cur]);
        // rnn partials = rnn_in @ WcatT, split-K 8x144, double-buffered
        gemm64s<144><<<dim3(BATCH / 64, HID / 64, KSPLIT), 256>>>(pr, KPAD, pW, prp,
                                                                  BATCH, HID);
        outred<<<BATCH, 256>>>(Wo, bo, ph[nxt], out, px[nxt], t);
    }
}